// round 16
// baseline (speedup 1.0000x reference)
#include <cuda_runtime.h>
#include <cuda_fp16.h>
#include <cstdint>
#include <math.h>

// Problem dims (fixed by the dataset)
#define B_ 4
#define S_ 4096
#define D_ 2048
#define DI_ 8192
#define MTOT (B_ * S_)   // 16384

// ---------------------------------------------------------------------------
// Static device scratch
// ---------------------------------------------------------------------------
__device__ __half g_xh[(size_t)MTOT * D_];    //  64 MB  x in fp16
__device__ __half g_wuph[(size_t)DI_ * D_];   //  32 MB  w_up fp16 [DI, D] K-major
__device__ __half g_wdh[(size_t)D_ * DI_];    //  32 MB  w_down fp16 [D, DI] K-major
__device__ __half g_h[(size_t)MTOT * DI_];    // 256 MB  gelu(up) intermediate

// ---------------------------------------------------------------------------
// GEMM config: CTA 128x128, 4 warps (2M x 2N), warp tile 64x64, BK=64,
// 3 stages (96 KB), 2 CTAs/SM. Round-10 mainloop (best known).
// GEMM1 folds the w_down int32->fp16 conversion into its epilogue.
// ---------------------------------------------------------------------------
constexpr int BM = 128;
constexpr int BN = 128;
constexpr int BK = 64;
constexpr int STAGES = 3;
constexpr int NTHREADS = 128;
constexpr int A_CHUNKS = BM * 8;
constexpr int B_CHUNKS = BN * 8;
constexpr int STAGE_CHUNKS = A_CHUNKS + B_CHUNKS;
constexpr int STAGE_BYTES = (BM + BN) * 128;     // 32 KB
constexpr int SMEM_BYTES = STAGES * STAGE_BYTES; // 96 KB dynamic

// ---------------------------------------------------------------------------
// PTX helpers
// ---------------------------------------------------------------------------
__device__ __forceinline__ uint32_t smem_u32(const void* p) {
    return (uint32_t)__cvta_generic_to_shared(p);
}
__device__ __forceinline__ void cp_async16(uint32_t dst, const void* src) {
    asm volatile("cp.async.cg.shared.global [%0], [%1], 16;\n"
                 :: "r"(dst), "l"(src) : "memory");
}
__device__ __forceinline__ void cp_commit() {
    asm volatile("cp.async.commit_group;\n" ::: "memory");
}
template <int N>
__device__ __forceinline__ void cp_wait() {
    asm volatile("cp.async.wait_group %0;\n" :: "n"(N) : "memory");
}
__device__ __forceinline__ void ldsm_x4(uint32_t& r0, uint32_t& r1, uint32_t& r2,
                                        uint32_t& r3, uint32_t addr) {
    asm volatile("ldmatrix.sync.aligned.m8n8.x4.shared.b16 {%0,%1,%2,%3}, [%4];\n"
                 : "=r"(r0), "=r"(r1), "=r"(r2), "=r"(r3) : "r"(addr));
}
__device__ __forceinline__ void mma16816(float* d, const uint32_t* a, const uint32_t* b) {
    asm volatile(
        "mma.sync.aligned.m16n8k16.row.col.f32.f16.f16.f32 "
        "{%0,%1,%2,%3}, {%4,%5,%6,%7}, {%8,%9}, {%0,%1,%2,%3};\n"
        : "+f"(d[0]), "+f"(d[1]), "+f"(d[2]), "+f"(d[3])
        : "r"(a[0]), "r"(a[1]), "r"(a[2]), "r"(a[3]), "r"(b[0]), "r"(b[1]));
}
__device__ __forceinline__ float gelu_exact(float v) {
    return 0.5f * v * (1.0f + erff(v * 0.70710678118654752f));
}

// ---------------------------------------------------------------------------
// Conversion kernel: x and w_up (w_down handled inside GEMM1).
// Each thread handles 4 PAIRS of adjacent float4 groups (8 independent
// evict-first loads, MLP=8), emitting one 16B store per pair (STG.128).
// Block covers 2048 float4 groups.
// ---------------------------------------------------------------------------
constexpr int XV    = (MTOT * D_) / 4;    // float4 groups (8M)
constexpr int WUPV  = (DI_ * D_) / 4;     // (4M)
constexpr int XB8   = XV / 2048;          // blocks covering x    (256 thr x 8)
constexpr int WUPB8 = WUPV / 2048;        // blocks covering w_up

__global__ void cvt_xw_kernel(const float* __restrict__ x,
                              const float* __restrict__ w_up) {
    int b = blockIdx.x;
    const float4* src;
    uint4* dst;
    int gbase;                          // first float4-group of this thread
    if (b < XB8) {
        src = reinterpret_cast<const float4*>(x);
        dst = reinterpret_cast<uint4*>(g_xh);
        gbase = b * 2048 + 2 * threadIdx.x;
    } else {
        src = reinterpret_cast<const float4*>(w_up);
        dst = reinterpret_cast<uint4*>(g_wuph);
        gbase = (b - XB8) * 2048 + 2 * threadIdx.x;
    }
    float4 v[8];
#pragma unroll
    for (int i = 0; i < 4; ++i) {       // 8 independent loads, front-batched
        v[2 * i]     = __ldcs(&src[gbase + i * 512]);
        v[2 * i + 1] = __ldcs(&src[gbase + i * 512 + 1]);
    }
#pragma unroll
    for (int i = 0; i < 4; ++i) {
        __half2 h0 = __floats2half2_rn(v[2 * i].x,     v[2 * i].y);
        __half2 h1 = __floats2half2_rn(v[2 * i].z,     v[2 * i].w);
        __half2 h2 = __floats2half2_rn(v[2 * i + 1].x, v[2 * i + 1].y);
        __half2 h3 = __floats2half2_rn(v[2 * i + 1].z, v[2 * i + 1].w);
        uint4 o;
        o.x = *reinterpret_cast<uint32_t*>(&h0);
        o.y = *reinterpret_cast<uint32_t*>(&h1);
        o.z = *reinterpret_cast<uint32_t*>(&h2);
        o.w = *reinterpret_cast<uint32_t*>(&h3);
        dst[(gbase >> 1) + i * 256] = o;   // 16B store, fully coalesced
    }
}

// ---------------------------------------------------------------------------
// Tiled fp16 GEMM, fused epilogue, cross-tile pipelined mainloop (round-10):
//   Tile body:  loads(kt+2); ldsm1/mma0; ldsm2/mma1; ldsm3/mma0;
//               cp_wait; BAR; ldsm0'(kt+1); mma1.
// BYTE-IDENTICAL to rounds 14/15 (protected asset).
// ---------------------------------------------------------------------------
template <int KDIM, int NDIM, bool IS_GEMM1>
__global__ void __launch_bounds__(NTHREADS, 2)
ffn_gemm_kernel(const float* __restrict__ bias,
                const float* __restrict__ scale,
                float* __restrict__ outp,
                const int* __restrict__ wdq)
{
    extern __shared__ uint4 smem[];   // [STAGES][(BM+BN)*8] 16B chunks
    __shared__ float s_bias[BN];
    __shared__ float s_scale[BN];

    const __half* Ag = IS_GEMM1 ? g_xh   : g_h;
    const __half* Bg = IS_GEMM1 ? g_wuph : g_wdh;

    const int m0 = blockIdx.y * BM;
    const int n0 = blockIdx.x * BN;
    const int tid = threadIdx.x;
    const int wid = tid >> 5;
    const int lane = tid & 31;
    const int wm = (wid & 1) * 64;
    const int wn = (wid >> 1) * 64;

    float acc[4][8][4];
#pragma unroll
    for (int mt = 0; mt < 4; ++mt)
#pragma unroll
        for (int nt = 0; nt < 8; ++nt)
#pragma unroll
            for (int i = 0; i < 4; ++i) acc[mt][nt][i] = 0.0f;

    constexpr int KTILES = KDIM / BK;

    // ---- Hoisted per-thread load addressing ----
    const int rBase = tid >> 3;
    const int cIdx  = tid & 7;
    const int cSw   = cIdx ^ (rBase & 7);
    const __half* aSrc0 = Ag + (size_t)(m0 + rBase) * KDIM + cIdx * 8;
    const __half* bSrc0 = Bg + (size_t)(n0 + rBase) * KDIM + cIdx * 8;
    const int dstBase = rBase * 8 + cSw;

    auto load_stage = [&](int s, int kt) {
        const __half* aS = aSrc0 + kt * BK;
        const __half* bS = bSrc0 + kt * BK;
        uint4* Ad = smem + s * STAGE_CHUNKS + dstBase;
        uint4* Bd = Ad + A_CHUNKS;
#pragma unroll
        for (int i = 0; i < A_CHUNKS / NTHREADS; ++i)
            cp_async16(smem_u32(Ad + i * 128), aS + (size_t)i * 16 * KDIM);
#pragma unroll
        for (int i = 0; i < B_CHUNKS / NTHREADS; ++i)
            cp_async16(smem_u32(Bd + i * 128), bS + (size_t)i * 16 * KDIM);
    };

    // Fixed per-thread LDSM indices
    const int rowA0 = wm + (lane & 15);
    const int rowB0 = wn + ((lane >> 4) << 3) + (lane & 7);
    const int cA = (lane >> 4);
    const int cB = ((lane >> 3) & 1);

    uint32_t fA[2][4][4];
    uint32_t fB[2][4][4];

    auto ldsm_kk = [&](const uint4* Aa, const uint4* Ba, int kk, int buf) {
#pragma unroll
        for (int mt = 0; mt < 4; ++mt) {
            int row = rowA0 + mt * 16;
            int c = kk * 2 + cA;
            ldsm_x4(fA[buf][mt][0], fA[buf][mt][1], fA[buf][mt][2], fA[buf][mt][3],
                    smem_u32(Aa + row * 8 + (c ^ (row & 7))));
        }
#pragma unroll
        for (int nt2 = 0; nt2 < 4; ++nt2) {
            int row = rowB0 + nt2 * 16;
            int c = kk * 2 + cB;
            ldsm_x4(fB[buf][nt2][0], fB[buf][nt2][1], fB[buf][nt2][2], fB[buf][nt2][3],
                    smem_u32(Ba + row * 8 + (c ^ (row & 7))));
        }
    };

    auto mma_kk = [&](int buf) {
#pragma unroll
        for (int mt = 0; mt < 4; ++mt)
#pragma unroll
            for (int nt = 0; nt < 8; ++nt)
                mma16816(acc[mt][nt], fA[buf][mt], &fB[buf][nt >> 1][(nt & 1) * 2]);
    };

    // Prologue: fill STAGES-1 stages; preload bias/scale tiles into smem.
#pragma unroll
    for (int s = 0; s < STAGES - 1; ++s) {
        load_stage(s, s);
        cp_commit();
    }
    if (tid < BN) {
        s_bias[tid] = bias[n0 + tid];
        s_scale[tid] = IS_GEMM1 ? 0.0f : scale[n0 + tid];
    }
    cp_wait<STAGES - 2>();
    __syncthreads();
    ldsm_kk(smem, smem + A_CHUNKS, 0, 0);

    for (int kt = 0; kt < KTILES; ++kt) {
        const uint4* Aa = smem + (kt % STAGES) * STAGE_CHUNKS;
        const uint4* Ba = Aa + A_CHUNKS;

        int ls = kt + STAGES - 1;
        if (ls < KTILES) load_stage(ls % STAGES, ls);
        cp_commit();

        ldsm_kk(Aa, Ba, 1, 1); mma_kk(0);
        ldsm_kk(Aa, Ba, 2, 0); mma_kk(1);
        ldsm_kk(Aa, Ba, 3, 1); mma_kk(0);

        cp_wait<STAGES - 2>();
        __syncthreads();
        if (kt + 1 < KTILES) {
            const uint4* An = smem + ((kt + 1) % STAGES) * STAGE_CHUNKS;
            ldsm_kk(An, An + A_CHUNKS, 0, 0);
        }
        mma_kk(1);
    }

    // ------------------------------------------------------------------ epilogue
    const int r0g = m0 + wm + (lane >> 2);
    const int lc0 = wn + ((lane & 3) << 1);
    const int c0g = n0 + lc0;

    if (IS_GEMM1) {
#pragma unroll
        for (int mt = 0; mt < 4; ++mt)
#pragma unroll
            for (int hrow = 0; hrow < 2; ++hrow) {
                int row = r0g + mt * 16 + hrow * 8;
#pragma unroll
                for (int nt = 0; nt < 8; ++nt) {
                    int lc = lc0 + nt * 8;
                    float v0 = acc[mt][nt][hrow * 2]     + s_bias[lc];
                    float v1 = acc[mt][nt][hrow * 2 + 1] + s_bias[lc + 1];
                    v0 = gelu_exact(v0);
                    v1 = gelu_exact(v1);
                    *reinterpret_cast<__half2*>(&g_h[(size_t)row * NDIM + c0g + nt * 8]) =
                        __floats2half2_rn(v0, v1);
                }
            }

        // ---- Folded w_down int32 -> fp16 conversion (grid-strided) ----
        {
            const int cta = blockIdx.y * gridDim.x + blockIdx.x;      // 0..8191
            const int base = cta * NTHREADS * 4 + tid;                // int4 index
            const int4* src = reinterpret_cast<const int4*>(wdq);
            __half2* dst = reinterpret_cast<__half2*>(g_wdh);
#pragma unroll
            for (int i = 0; i < 4; ++i) {
                int idx = base + i * NTHREADS;
                int4 v = __ldcs(&src[idx]);
                dst[2 * idx]     = __floats2half2_rn((float)v.x, (float)v.y);
                dst[2 * idx + 1] = __floats2half2_rn((float)v.z, (float)v.w);
            }
        }
    } else {
#pragma unroll
        for (int mt = 0; mt < 4; ++mt)
#pragma unroll
            for (int hrow = 0; hrow < 2; ++hrow) {
                int row = r0g + mt * 16 + hrow * 8;
#pragma unroll
                for (int nt = 0; nt < 8; ++nt) {
                    int lc = lc0 + nt * 8;
                    float2 o;
                    o.x = acc[mt][nt][hrow * 2]     * s_scale[lc]     + s_bias[lc];
                    o.y = acc[mt][nt][hrow * 2 + 1] * s_scale[lc + 1] + s_bias[lc + 1];
                    *reinterpret_cast<float2*>(&outp[(size_t)row * NDIM + c0g + nt * 8]) = o;
                }
            }
    }
}

// ---------------------------------------------------------------------------
// Launch
// ---------------------------------------------------------------------------
extern "C" void kernel_launch(void* const* d_in, const int* in_sizes, int n_in,
                              void* d_out, int out_size)
{
    const float* x            = (const float*)d_in[0];  // [B,S,D]
    const float* w_up         = (const float*)d_in[1];  // [DI,D]
    const float* b_up         = (const float*)d_in[2];  // [DI]
    const int*   w_down_q     = (const int*)  d_in[3];  // [D,DI] int32
    const float* w_down_scale = (const float*)d_in[4];  // [D]
    const float* b_down       = (const float*)d_in[5];  // [D]
    float* out = (float*)d_out;                         // [B,S,D]

    cvt_xw_kernel<<<XB8 + WUPB8, 256>>>(x, w_up);

    cudaFuncSetAttribute(ffn_gemm_kernel<D_, DI_, true>,
                         cudaFuncAttributeMaxDynamicSharedMemorySize, SMEM_BYTES);
    ffn_gemm_kernel<D_, DI_, true>
        <<<dim3(DI_ / BN, MTOT / BM), NTHREADS, SMEM_BYTES>>>(b_up, nullptr, nullptr, w_down_q);

    cudaFuncSetAttribute(ffn_gemm_kernel<DI_, D_, false>,
                         cudaFuncAttributeMaxDynamicSharedMemorySize, SMEM_BYTES);
    ffn_gemm_kernel<DI_, D_, false>
        <<<dim3(D_ / BN, MTOT / BM), NTHREADS, SMEM_BYTES>>>(b_down, w_down_scale, out, nullptr);
}

// round 17
// speedup vs baseline: 1.0035x; 1.0035x over previous
#include <cuda_runtime.h>
#include <cuda_fp16.h>
#include <cstdint>
#include <math.h>

// Problem dims (fixed by the dataset)
#define B_ 4
#define S_ 4096
#define D_ 2048
#define DI_ 8192
#define MTOT (B_ * S_)   // 16384

// ---------------------------------------------------------------------------
// Static device scratch
// ---------------------------------------------------------------------------
__device__ __half g_xh[(size_t)MTOT * D_];    //  64 MB  x in fp16
__device__ __half g_wuph[(size_t)DI_ * D_];   //  32 MB  w_up fp16 [DI, D] K-major
__device__ __half g_wdh[(size_t)D_ * DI_];    //  32 MB  w_down fp16 [D, DI] K-major
__device__ __half g_h[(size_t)MTOT * DI_];    // 256 MB  gelu(up) intermediate

// ---------------------------------------------------------------------------
// GEMM config: CTA 128x128, 4 warps (2M x 2N), warp tile 64x64, BK=64,
// 3 stages (96 KB), 2 CTAs/SM. Round-10 mainloop (best known).
// GEMM1 folds the w_down int32->fp16 conversion into its epilogue.
// ---------------------------------------------------------------------------
constexpr int BM = 128;
constexpr int BN = 128;
constexpr int BK = 64;
constexpr int STAGES = 3;
constexpr int NTHREADS = 128;
constexpr int A_CHUNKS = BM * 8;
constexpr int B_CHUNKS = BN * 8;
constexpr int STAGE_CHUNKS = A_CHUNKS + B_CHUNKS;
constexpr int STAGE_BYTES = (BM + BN) * 128;     // 32 KB
constexpr int SMEM_BYTES = STAGES * STAGE_BYTES; // 96 KB dynamic

// ---------------------------------------------------------------------------
// PTX helpers
// ---------------------------------------------------------------------------
__device__ __forceinline__ uint32_t smem_u32(const void* p) {
    return (uint32_t)__cvta_generic_to_shared(p);
}
__device__ __forceinline__ void cp_async16(uint32_t dst, const void* src) {
    asm volatile("cp.async.cg.shared.global [%0], [%1], 16;\n"
                 :: "r"(dst), "l"(src) : "memory");
}
__device__ __forceinline__ void cp_commit() {
    asm volatile("cp.async.commit_group;\n" ::: "memory");
}
template <int N>
__device__ __forceinline__ void cp_wait() {
    asm volatile("cp.async.wait_group %0;\n" :: "n"(N) : "memory");
}
__device__ __forceinline__ void ldsm_x4(uint32_t& r0, uint32_t& r1, uint32_t& r2,
                                        uint32_t& r3, uint32_t addr) {
    asm volatile("ldmatrix.sync.aligned.m8n8.x4.shared.b16 {%0,%1,%2,%3}, [%4];\n"
                 : "=r"(r0), "=r"(r1), "=r"(r2), "=r"(r3) : "r"(addr));
}
__device__ __forceinline__ void mma16816(float* d, const uint32_t* a, const uint32_t* b) {
    asm volatile(
        "mma.sync.aligned.m16n8k16.row.col.f32.f16.f16.f32 "
        "{%0,%1,%2,%3}, {%4,%5,%6,%7}, {%8,%9}, {%0,%1,%2,%3};\n"
        : "+f"(d[0]), "+f"(d[1]), "+f"(d[2]), "+f"(d[3])
        : "r"(a[0]), "r"(a[1]), "r"(a[2]), "r"(a[3]), "r"(b[0]), "r"(b[1]));
}
__device__ __forceinline__ float gelu_exact(float v) {
    return 0.5f * v * (1.0f + erff(v * 0.70710678118654752f));
}

// ---------------------------------------------------------------------------
// Conversion kernel: x and w_up (w_down handled inside GEMM1).
// MLP=4: each thread front-batches 4 independent float4 loads (evict-first)
// then writes 8 half2 pairs. Block covers 1024 float4 groups.
// ---------------------------------------------------------------------------
constexpr int XV   = (MTOT * D_) / 4;    // float4 groups
constexpr int WUPV = (DI_ * D_) / 4;
constexpr int XB4  = XV / 1024;          // blocks covering x   (256 thr x 4)
constexpr int WUPB4 = WUPV / 1024;       // blocks covering w_up

__global__ void cvt_xw_kernel(const float* __restrict__ x,
                              const float* __restrict__ w_up) {
    int b = blockIdx.x;
    const float4* src;
    __half2* dst;
    int base;
    if (b < XB4) {
        src = reinterpret_cast<const float4*>(x);
        dst = reinterpret_cast<__half2*>(g_xh);
        base = b * 1024 + threadIdx.x;
    } else {
        src = reinterpret_cast<const float4*>(w_up);
        dst = reinterpret_cast<__half2*>(g_wuph);
        base = (b - XB4) * 1024 + threadIdx.x;
    }
    float4 v[4];
#pragma unroll
    for (int i = 0; i < 4; ++i)
        v[i] = __ldcs(&src[base + i * 256]);
#pragma unroll
    for (int i = 0; i < 4; ++i) {
        int idx = base + i * 256;
        dst[2 * idx]     = __floats2half2_rn(v[i].x, v[i].y);
        dst[2 * idx + 1] = __floats2half2_rn(v[i].z, v[i].w);
    }
}

// ---------------------------------------------------------------------------
// Tiled fp16 GEMM, fused epilogue, cross-tile pipelined mainloop (round-10):
//   Tile body:  loads(kt+2); ldsm1/mma0; ldsm2/mma1; ldsm3/mma0;
//               cp_wait; BAR; ldsm0'(kt+1); mma1.
// ---------------------------------------------------------------------------
template <int KDIM, int NDIM, bool IS_GEMM1>
__global__ void __launch_bounds__(NTHREADS, 2)
ffn_gemm_kernel(const float* __restrict__ bias,
                const float* __restrict__ scale,
                float* __restrict__ outp,
                const int* __restrict__ wdq)
{
    extern __shared__ uint4 smem[];   // [STAGES][(BM+BN)*8] 16B chunks
    __shared__ float s_bias[BN];
    __shared__ float s_scale[BN];

    const __half* Ag = IS_GEMM1 ? g_xh   : g_h;
    const __half* Bg = IS_GEMM1 ? g_wuph : g_wdh;

    const int m0 = blockIdx.y * BM;
    const int n0 = blockIdx.x * BN;
    const int tid = threadIdx.x;
    const int wid = tid >> 5;
    const int lane = tid & 31;
    const int wm = (wid & 1) * 64;
    const int wn = (wid >> 1) * 64;

    float acc[4][8][4];
#pragma unroll
    for (int mt = 0; mt < 4; ++mt)
#pragma unroll
        for (int nt = 0; nt < 8; ++nt)
#pragma unroll
            for (int i = 0; i < 4; ++i) acc[mt][nt][i] = 0.0f;

    constexpr int KTILES = KDIM / BK;

    // ---- Hoisted per-thread load addressing ----
    const int rBase = tid >> 3;
    const int cIdx  = tid & 7;
    const int cSw   = cIdx ^ (rBase & 7);
    const __half* aSrc0 = Ag + (size_t)(m0 + rBase) * KDIM + cIdx * 8;
    const __half* bSrc0 = Bg + (size_t)(n0 + rBase) * KDIM + cIdx * 8;
    const int dstBase = rBase * 8 + cSw;

    auto load_stage = [&](int s, int kt) {
        const __half* aS = aSrc0 + kt * BK;
        const __half* bS = bSrc0 + kt * BK;
        uint4* Ad = smem + s * STAGE_CHUNKS + dstBase;
        uint4* Bd = Ad + A_CHUNKS;
#pragma unroll
        for (int i = 0; i < A_CHUNKS / NTHREADS; ++i)
            cp_async16(smem_u32(Ad + i * 128), aS + (size_t)i * 16 * KDIM);
#pragma unroll
        for (int i = 0; i < B_CHUNKS / NTHREADS; ++i)
            cp_async16(smem_u32(Bd + i * 128), bS + (size_t)i * 16 * KDIM);
    };

    // Fixed per-thread LDSM indices
    const int rowA0 = wm + (lane & 15);
    const int rowB0 = wn + ((lane >> 4) << 3) + (lane & 7);
    const int cA = (lane >> 4);
    const int cB = ((lane >> 3) & 1);

    uint32_t fA[2][4][4];
    uint32_t fB[2][4][4];

    auto ldsm_kk = [&](const uint4* Aa, const uint4* Ba, int kk, int buf) {
#pragma unroll
        for (int mt = 0; mt < 4; ++mt) {
            int row = rowA0 + mt * 16;
            int c = kk * 2 + cA;
            ldsm_x4(fA[buf][mt][0], fA[buf][mt][1], fA[buf][mt][2], fA[buf][mt][3],
                    smem_u32(Aa + row * 8 + (c ^ (row & 7))));
        }
#pragma unroll
        for (int nt2 = 0; nt2 < 4; ++nt2) {
            int row = rowB0 + nt2 * 16;
            int c = kk * 2 + cB;
            ldsm_x4(fB[buf][nt2][0], fB[buf][nt2][1], fB[buf][nt2][2], fB[buf][nt2][3],
                    smem_u32(Ba + row * 8 + (c ^ (row & 7))));
        }
    };

    auto mma_kk = [&](int buf) {
#pragma unroll
        for (int mt = 0; mt < 4; ++mt)
#pragma unroll
            for (int nt = 0; nt < 8; ++nt)
                mma16816(acc[mt][nt], fA[buf][mt], &fB[buf][nt >> 1][(nt & 1) * 2]);
    };

    // Prologue: fill STAGES-1 stages; preload bias/scale tiles into smem.
#pragma unroll
    for (int s = 0; s < STAGES - 1; ++s) {
        load_stage(s, s);
        cp_commit();
    }
    if (tid < BN) {
        s_bias[tid] = bias[n0 + tid];
        s_scale[tid] = IS_GEMM1 ? 0.0f : scale[n0 + tid];
    }
    cp_wait<STAGES - 2>();
    __syncthreads();
    ldsm_kk(smem, smem + A_CHUNKS, 0, 0);

    for (int kt = 0; kt < KTILES; ++kt) {
        const uint4* Aa = smem + (kt % STAGES) * STAGE_CHUNKS;
        const uint4* Ba = Aa + A_CHUNKS;

        int ls = kt + STAGES - 1;
        if (ls < KTILES) load_stage(ls % STAGES, ls);
        cp_commit();

        ldsm_kk(Aa, Ba, 1, 1); mma_kk(0);
        ldsm_kk(Aa, Ba, 2, 0); mma_kk(1);
        ldsm_kk(Aa, Ba, 3, 1); mma_kk(0);

        cp_wait<STAGES - 2>();
        __syncthreads();
        if (kt + 1 < KTILES) {
            const uint4* An = smem + ((kt + 1) % STAGES) * STAGE_CHUNKS;
            ldsm_kk(An, An + A_CHUNKS, 0, 0);
        }
        mma_kk(1);
    }

    // ------------------------------------------------------------------ epilogue
    const int r0g = m0 + wm + (lane >> 2);
    const int lc0 = wn + ((lane & 3) << 1);
    const int c0g = n0 + lc0;

    if (IS_GEMM1) {
#pragma unroll
        for (int mt = 0; mt < 4; ++mt)
#pragma unroll
            for (int hrow = 0; hrow < 2; ++hrow) {
                int row = r0g + mt * 16 + hrow * 8;
#pragma unroll
                for (int nt = 0; nt < 8; ++nt) {
                    int lc = lc0 + nt * 8;
                    float v0 = acc[mt][nt][hrow * 2]     + s_bias[lc];
                    float v1 = acc[mt][nt][hrow * 2 + 1] + s_bias[lc + 1];
                    v0 = gelu_exact(v0);
                    v1 = gelu_exact(v1);
                    *reinterpret_cast<__half2*>(&g_h[(size_t)row * NDIM + c0g + nt * 8]) =
                        __floats2half2_rn(v0, v1);
                }
            }

        // ---- Folded w_down int32 -> fp16 conversion (grid-strided) ----
        {
            const int cta = blockIdx.y * gridDim.x + blockIdx.x;      // 0..8191
            const int base = cta * NTHREADS * 4 + tid;                // int4 index
            const int4* src = reinterpret_cast<const int4*>(wdq);
            __half2* dst = reinterpret_cast<__half2*>(g_wdh);
#pragma unroll
            for (int i = 0; i < 4; ++i) {
                int idx = base + i * NTHREADS;
                int4 v = __ldcs(&src[idx]);
                dst[2 * idx]     = __floats2half2_rn((float)v.x, (float)v.y);
                dst[2 * idx + 1] = __floats2half2_rn((float)v.z, (float)v.w);
            }
        }
    } else {
#pragma unroll
        for (int mt = 0; mt < 4; ++mt)
#pragma unroll
            for (int hrow = 0; hrow < 2; ++hrow) {
                int row = r0g + mt * 16 + hrow * 8;
#pragma unroll
                for (int nt = 0; nt < 8; ++nt) {
                    int lc = lc0 + nt * 8;
                    float2 o;
                    o.x = acc[mt][nt][hrow * 2]     * s_scale[lc]     + s_bias[lc];
                    o.y = acc[mt][nt][hrow * 2 + 1] * s_scale[lc + 1] + s_bias[lc + 1];
                    *reinterpret_cast<float2*>(&outp[(size_t)row * NDIM + c0g + nt * 8]) = o;
                }
            }
    }
}

// ---------------------------------------------------------------------------
// Launch
// ---------------------------------------------------------------------------
extern "C" void kernel_launch(void* const* d_in, const int* in_sizes, int n_in,
                              void* d_out, int out_size)
{
    const float* x            = (const float*)d_in[0];  // [B,S,D]
    const float* w_up         = (const float*)d_in[1];  // [DI,D]
    const float* b_up         = (const float*)d_in[2];  // [DI]
    const int*   w_down_q     = (const int*)  d_in[3];  // [D,DI] int32
    const float* w_down_scale = (const float*)d_in[4];  // [D]
    const float* b_down       = (const float*)d_in[5];  // [D]
    float* out = (float*)d_out;                         // [B,S,D]

    cvt_xw_kernel<<<XB4 + WUPB4, 256>>>(x, w_up);

    cudaFuncSetAttribute(ffn_gemm_kernel<D_, DI_, true>,
                         cudaFuncAttributeMaxDynamicSharedMemorySize, SMEM_BYTES);
    ffn_gemm_kernel<D_, DI_, true>
        <<<dim3(DI_ / BN, MTOT / BM), NTHREADS, SMEM_BYTES>>>(b_up, nullptr, nullptr, w_down_q);

    cudaFuncSetAttribute(ffn_gemm_kernel<DI_, D_, false>,
                         cudaFuncAttributeMaxDynamicSharedMemorySize, SMEM_BYTES);
    ffn_gemm_kernel<DI_, D_, false>
        <<<dim3(D_ / BN, MTOT / BM), NTHREADS, SMEM_BYTES>>>(b_down, w_down_scale, out, nullptr);
}